// round 8
// baseline (speedup 1.0000x reference)
#include <cuda_runtime.h>

#define Bn 4
#define Cn 64
#define On 64
#define Hn 128
#define Wn 128
#define KK 9
#define NPIX (Bn * Hn * Wn)

// Scratch (device globals: no allocation allowed)
__device__ float g_xT[(size_t)Bn * Hn * Wn * Cn];   // x in NHWC (16 MB)
__device__ float g_off[18 * NPIX];                  // offsets, plane layout [ch][pix]
__device__ float g_w2[KK * Cn * On];                // main weight as [k][c][o]

// ---------------- f32x2 packed helpers ----------------
__device__ __forceinline__ unsigned long long pack2(float lo, float hi) {
    unsigned long long r;
    asm("mov.b64 %0, {%1,%2};" : "=l"(r) : "f"(lo), "f"(hi));
    return r;
}
__device__ __forceinline__ unsigned long long pack1(float a) { return pack2(a, a); }
__device__ __forceinline__ void ffma2(unsigned long long& d, unsigned long long a, unsigned long long b) {
    asm("fma.rn.f32x2 %0, %1, %2, %0;" : "+l"(d) : "l"(a), "l"(b));
}
__device__ __forceinline__ float2 unpk2(unsigned long long v) {
    float2 r;
    asm("mov.b64 {%0,%1}, %2;" : "=f"(r.x), "=f"(r.y) : "l"(v));
    return r;
}

// ---------------------------------------------------------------------------
// Kernel 1: NCHW -> NHWC transpose of x
// ---------------------------------------------------------------------------
__global__ void transpose_k(const float* __restrict__ x) {
    __shared__ float tile[32][33];
    int w0 = blockIdx.x * 32;
    int c0 = blockIdx.y * 32;
    int bh = blockIdx.z;
    int b = bh >> 7, h = bh & 127;
    int tx = threadIdx.x, ty = threadIdx.y;
#pragma unroll
    for (int i = 0; i < 4; i++) {
        int c = c0 + ty + i * 8;
        tile[ty + i * 8][tx] = x[(((size_t)b * Cn + c) * Hn + h) * Wn + (w0 + tx)];
    }
    __syncthreads();
#pragma unroll
    for (int i = 0; i < 4; i++) {
        int w = w0 + ty + i * 8;
        g_xT[(((size_t)b * Hn + h) * Wn + w) * Cn + (c0 + tx)] = tile[tx][ty + i * 8];
    }
}

// ---------------------------------------------------------------------------
// Kernel 2: (O,C,3,3) -> g_w2[k][c][o]
// ---------------------------------------------------------------------------
__global__ void prep_w_k(const float* __restrict__ weight) {
    int d = blockIdx.x * blockDim.x + threadIdx.x;
    if (d >= KK * Cn * On) return;
    int k = d >> 12;
    int rem = d & 4095;
    int c = rem >> 6;
    int o = rem & 63;
    g_w2[d] = weight[(o * Cn + c) * KK + k];
}

// ---------------------------------------------------------------------------
// Kernel 3: offset conv (3x3 SAME, 64 -> 18 ch), reads x in NCHW directly
// (lane-coalesced), weights in smem padded rows of 20 floats, f32x2 accum.
// Output in plane layout g_off[ch][pix]. grid 256, block 256.
// ---------------------------------------------------------------------------
__global__ __launch_bounds__(256) void offset_conv_k(
    const float* __restrict__ x,
    const float* __restrict__ offset_w,   // (18, 64, 3, 3)
    const float* __restrict__ offset_b)   // (18,)
{
    __shared__ float wS[KK * Cn * 20];    // [tap*64+c][20] rows (18 used), 46080 B

    int tid = threadIdx.x;
    for (int s = tid; s < KK * Cn * 18; s += 256) {
        int j = s % 18;
        int t2 = s / 18;
        int c = t2 & 63;
        int tap = t2 >> 6;
        wS[t2 * 20 + j] = offset_w[(j * Cn + c) * KK + tap];
    }
    __syncthreads();

    int pid = blockIdx.x * 256 + tid;     // pixel id
    int b = pid >> 14;
    int y = (pid >> 7) & 127;
    int xw = pid & 127;

    unsigned long long acc[9];
#pragma unroll
    for (int j = 0; j < 9; j++) acc[j] = pack2(offset_b[2 * j], offset_b[2 * j + 1]);

    const float* xbase = x + (size_t)b * Cn * Hn * Wn;

    for (int ky = 0; ky < 3; ky++) {
        int yy = y - 1 + ky;
        if (yy < 0 || yy >= Hn) continue;
        for (int kx = 0; kx < 3; kx++) {
            int xx = xw - 1 + kx;
            if (xx < 0 || xx >= Wn) continue;
            int tap = ky * 3 + kx;
            const float* xc = xbase + yy * Wn + xx;          // stride Hn*Wn per c
            const float* wrow = wS + tap * Cn * 20;
#pragma unroll 4
            for (int c = 0; c < Cn; c++) {
                float a = __ldg(xc + (size_t)c * (Hn * Wn));
                unsigned long long ap = pack1(a);
                const float* wr = wrow + c * 20;              // 80B aligned
                ulonglong2 w01 = *(const ulonglong2*)(wr);
                ulonglong2 w23 = *(const ulonglong2*)(wr + 4);
                ulonglong2 w45 = *(const ulonglong2*)(wr + 8);
                ulonglong2 w67 = *(const ulonglong2*)(wr + 12);
                unsigned long long w8 = *(const unsigned long long*)(wr + 16);
                ffma2(acc[0], ap, w01.x);
                ffma2(acc[1], ap, w01.y);
                ffma2(acc[2], ap, w23.x);
                ffma2(acc[3], ap, w23.y);
                ffma2(acc[4], ap, w45.x);
                ffma2(acc[5], ap, w45.y);
                ffma2(acc[6], ap, w67.x);
                ffma2(acc[7], ap, w67.y);
                ffma2(acc[8], ap, w8);
            }
        }
    }

#pragma unroll
    for (int j = 0; j < 9; j++) {
        float2 v = unpk2(acc[j]);
        g_off[(2 * j) * NPIX + pid] = v.x;
        g_off[(2 * j + 1) * NPIX + pid] = v.y;
    }
}

// ---------------------------------------------------------------------------
// Kernel 4: deformable conv. CTA = 128 px (16w x 8h) x 64 o, 256 threads.
// Per tap: gather bilinear S_k -> sA[px][68] (16 lanes per pixel, coalesced),
// stage W_k[c][o] -> sW, then rank-64 update: thread = 2 px (pg, pg+64) x
// 16 o (og*4 + 16q + r), f32x2 accumulators.
// grid (8, 16, 4), block 256, dynamic smem 51200 B.
// ---------------------------------------------------------------------------
#define TS_W 16
#define TS_H 8
#define TPX 128
#define SA_STRIDE 68

__global__ __launch_bounds__(256) void deform_k(
    const float* __restrict__ bias,
    float* __restrict__ out)
{
    extern __shared__ float dsm[];
    float* sA = dsm;                        // 128 * 68 floats
    float* sW = dsm + TPX * SA_STRIDE;      // 64 * 64 floats

    int tid = threadIdx.x;
    int x0t = blockIdx.x * TS_W;
    int y0t = blockIdx.y * TS_H;
    int b = blockIdx.z;

    // gather mapping: 16 lanes per pixel (one float4 chunk each)
    int gchunk = tid & 15;
    int gpx0 = tid >> 4;                    // 0..15, iterate +16
    int cc = gchunk * 4;

    // gemm mapping
    int og = tid & 3;
    int pg = tid >> 2;                      // 0..63

    unsigned long long acc0[8], acc1[8];
#pragma unroll
    for (int j = 0; j < 8; j++) { acc0[j] = 0ull; acc1[j] = 0ull; }

    const float* xb = g_xT + (size_t)b * Hn * Wn * Cn;

    for (int k = 0; k < KK; k++) {
        __syncthreads();

        // stage W_k[c][o]
        {
            const float4* src = (const float4*)(g_w2 + k * Cn * On);
            float4* dst = (float4*)sW;
#pragma unroll
            for (int r = 0; r < 4; r++) dst[tid + r * 256] = src[tid + r * 256];
        }

        // gather S_k
        int ky = k / 3, kx = k - ky * 3;
#pragma unroll
        for (int it = 0; it < 8; it++) {
            int p = it * 16 + gpx0;
            int lw = p & 15, lh = p >> 4;
            int gx = x0t + lw, gy = y0t + lh;
            int gpix = (b * Hn + gy) * Wn + gx;
            float offY = __ldg(g_off + (2 * k) * NPIX + gpix);
            float offX = __ldg(g_off + (2 * k + 1) * NPIX + gpix);
            float pfy = (float)(gy - 1 + ky) + offY;
            float pfx = (float)(gx - 1 + kx) + offX;
            float fy0 = floorf(pfy), fx0 = floorf(pfx);
            float wy1 = pfy - fy0, wx1 = pfx - fx0;
            float wy0 = 1.f - wy1, wx0 = 1.f - wx1;
            int iy0 = (int)fy0, ix0 = (int)fx0;
            int iy1 = iy0 + 1, ix1 = ix0 + 1;
            bool vy0 = (iy0 >= 0) & (iy0 < Hn);
            bool vy1 = (iy1 >= 0) & (iy1 < Hn);
            bool vx0 = (ix0 >= 0) & (ix0 < Wn);
            bool vx1 = (ix1 >= 0) & (ix1 < Wn);
            int cy0 = min(max(iy0, 0), Hn - 1);
            int cy1 = min(max(iy1, 0), Hn - 1);
            int cx0 = min(max(ix0, 0), Wn - 1);
            int cx1 = min(max(ix1, 0), Wn - 1);

            const float* bp = xb + cc;
            float4 r = make_float4(0.f, 0.f, 0.f, 0.f);
            if (vy0 & vx0) {
                float4 t = *(const float4*)(bp + (cy0 * Wn + cx0) * Cn);
                float w = wy0 * wx0;
                r.x += w * t.x; r.y += w * t.y; r.z += w * t.z; r.w += w * t.w;
            }
            if (vy0 & vx1) {
                float4 t = *(const float4*)(bp + (cy0 * Wn + cx1) * Cn);
                float w = wy0 * wx1;
                r.x += w * t.x; r.y += w * t.y; r.z += w * t.z; r.w += w * t.w;
            }
            if (vy1 & vx0) {
                float4 t = *(const float4*)(bp + (cy1 * Wn + cx0) * Cn);
                float w = wy1 * wx0;
                r.x += w * t.x; r.y += w * t.y; r.z += w * t.z; r.w += w * t.w;
            }
            if (vy1 & vx1) {
                float4 t = *(const float4*)(bp + (cy1 * Wn + cx1) * Cn);
                float w = wy1 * wx1;
                r.x += w * t.x; r.y += w * t.y; r.z += w * t.z; r.w += w * t.w;
            }
            *(float4*)(sA + p * SA_STRIDE + cc) = r;
        }

        __syncthreads();

        // rank-64 update
        const float* a0p = sA + pg * SA_STRIDE;
        const float* a1p = sA + (pg + 64) * SA_STRIDE;
        const float* bcol = sW + og * 4;
        for (int c = 0; c < Cn; c += 4) {
            float4 a0v = *(const float4*)(a0p + c);
            float4 a1v = *(const float4*)(a1p + c);
#pragma unroll
            for (int u = 0; u < 4; u++) {
                float av0 = (u == 0) ? a0v.x : (u == 1) ? a0v.y : (u == 2) ? a0v.z : a0v.w;
                float av1 = (u == 0) ? a1v.x : (u == 1) ? a1v.y : (u == 2) ? a1v.z : a1v.w;
                unsigned long long ap0 = pack1(av0);
                unsigned long long ap1 = pack1(av1);
                const float* br = bcol + (c + u) * On;
#pragma unroll
                for (int q = 0; q < 4; q++) {
                    ulonglong2 bv = *(const ulonglong2*)(br + q * 16);
                    ffma2(acc0[q * 2], ap0, bv.x);
                    ffma2(acc0[q * 2 + 1], ap0, bv.y);
                    ffma2(acc1[q * 2], ap1, bv.x);
                    ffma2(acc1[q * 2 + 1], ap1, bv.y);
                }
            }
        }
    }

    // epilogue: transpose through smem (reuse sA as [o][128]) for coalesced STG
    __syncthreads();
#pragma unroll
    for (int q = 0; q < 4; q++) {
#pragma unroll
        for (int s = 0; s < 2; s++) {
            int o = og * 4 + q * 16 + s * 2;
            float2 v0 = unpk2(acc0[q * 2 + s]);
            float2 v1 = unpk2(acc1[q * 2 + s]);
            sA[o * TPX + pg] = v0.x;
            sA[(o + 1) * TPX + pg] = v0.y;
            sA[o * TPX + pg + 64] = v1.x;
            sA[(o + 1) * TPX + pg + 64] = v1.y;
        }
    }
    __syncthreads();

#pragma unroll
    for (int r = 0; r < 32; r++) {
        int i = r * 256 + tid;           // 0..8191
        int o = i >> 7;
        int p = i & 127;
        int lw = p & 15, lh = p >> 4;
        float v = sA[o * TPX + p] + __ldg(bias + o);
        out[(((size_t)b * On + o) * Hn + (y0t + lh)) * Wn + (x0t + lw)] = v;
    }
}

// ---------------------------------------------------------------------------
extern "C" void kernel_launch(void* const* d_in, const int* in_sizes, int n_in,
                              void* d_out, int out_size) {
    const float* x        = (const float*)d_in[0];   // (4,64,128,128)
    const float* offset_w = (const float*)d_in[1];   // (18,64,3,3)
    const float* offset_b = (const float*)d_in[2];   // (18,)
    const float* weight   = (const float*)d_in[3];   // (64,64,3,3)
    const float* bias     = (const float*)d_in[4];   // (64,)
    float* out = (float*)d_out;                      // (4,64,128,128)

    cudaFuncSetAttribute(deform_k, cudaFuncAttributeMaxDynamicSharedMemorySize, 56 * 1024);

    transpose_k<<<dim3(Wn / 32, Cn / 32, Bn * Hn), dim3(32, 8)>>>(x);
    prep_w_k<<<(KK * Cn * On + 255) / 256, 256>>>(weight);
    offset_conv_k<<<(NPIX) / 256, 256>>>(x, offset_w, offset_b);
    deform_k<<<dim3(Wn / TS_W, Hn / TS_H, Bn), 256, TPX * SA_STRIDE * 4 + Cn * On * 4>>>(bias, out);
}

// round 10
// speedup vs baseline: 1.6115x; 1.6115x over previous
#include <cuda_runtime.h>

#define Bn 4
#define Cn 64
#define On 64
#define Hn 128
#define Wn 128
#define KK 9
#define NPIX (Bn * Hn * Wn)

// Scratch (device globals: no allocation allowed)
__device__ float g_xT[(size_t)Bn * Hn * Wn * Cn];   // x in NHWC (16 MB)
__device__ float g_off[18 * NPIX];                  // offsets, plane layout [ch][pix]
__device__ float g_w2[KK * Cn * On];                // main weight as [k][c][o]

// ---------------- f32x2 packed helpers ----------------
__device__ __forceinline__ unsigned long long pack2(float lo, float hi) {
    unsigned long long r;
    asm("mov.b64 %0, {%1,%2};" : "=l"(r) : "f"(lo), "f"(hi));
    return r;
}
__device__ __forceinline__ unsigned long long pack1(float a) { return pack2(a, a); }
__device__ __forceinline__ void ffma2(unsigned long long& d, unsigned long long a, unsigned long long b) {
    asm("fma.rn.f32x2 %0, %1, %2, %0;" : "+l"(d) : "l"(a), "l"(b));
}
__device__ __forceinline__ float2 unpk2(unsigned long long v) {
    float2 r;
    asm("mov.b64 {%0,%1}, %2;" : "=f"(r.x), "=f"(r.y) : "l"(v));
    return r;
}

// ---------------------------------------------------------------------------
// Kernel 1: NCHW -> NHWC transpose of x
// ---------------------------------------------------------------------------
__global__ void transpose_k(const float* __restrict__ x) {
    __shared__ float tile[32][33];
    int w0 = blockIdx.x * 32;
    int c0 = blockIdx.y * 32;
    int bh = blockIdx.z;
    int b = bh >> 7, h = bh & 127;
    int tx = threadIdx.x, ty = threadIdx.y;
#pragma unroll
    for (int i = 0; i < 4; i++) {
        int c = c0 + ty + i * 8;
        tile[ty + i * 8][tx] = x[(((size_t)b * Cn + c) * Hn + h) * Wn + (w0 + tx)];
    }
    __syncthreads();
#pragma unroll
    for (int i = 0; i < 4; i++) {
        int w = w0 + ty + i * 8;
        g_xT[(((size_t)b * Hn + h) * Wn + w) * Cn + (c0 + tx)] = tile[tx][ty + i * 8];
    }
}

// ---------------------------------------------------------------------------
// Kernel 2: (O,C,3,3) -> g_w2[k][c][o]
// ---------------------------------------------------------------------------
__global__ void prep_w_k(const float* __restrict__ weight) {
    int d = blockIdx.x * blockDim.x + threadIdx.x;
    if (d >= KK * Cn * On) return;
    int k = d >> 12;
    int rem = d & 4095;
    int c = rem >> 6;
    int o = rem & 63;
    g_w2[d] = weight[(o * Cn + c) * KK + k];
}

// ---------------------------------------------------------------------------
// Kernel 3: offset conv (3x3 SAME, 64 -> 18 ch), reads x in NCHW directly
// (lane-coalesced), weights in smem padded rows of 20 floats, f32x2 accum.
// Output in plane layout g_off[ch][pix]. grid 256, block 256.
// ---------------------------------------------------------------------------
__global__ __launch_bounds__(256) void offset_conv_k(
    const float* __restrict__ x,
    const float* __restrict__ offset_w,   // (18, 64, 3, 3)
    const float* __restrict__ offset_b)   // (18,)
{
    __shared__ float wS[KK * Cn * 20];    // [tap*64+c][20] rows (18 used), 46080 B

    int tid = threadIdx.x;
    for (int s = tid; s < KK * Cn * 18; s += 256) {
        int j = s % 18;
        int t2 = s / 18;
        int c = t2 & 63;
        int tap = t2 >> 6;
        wS[t2 * 20 + j] = offset_w[(j * Cn + c) * KK + tap];
    }
    __syncthreads();

    int pid = blockIdx.x * 256 + tid;     // pixel id
    int b = pid >> 14;
    int y = (pid >> 7) & 127;
    int xw = pid & 127;

    unsigned long long acc[9];
#pragma unroll
    for (int j = 0; j < 9; j++) acc[j] = pack2(offset_b[2 * j], offset_b[2 * j + 1]);

    const float* xbase = x + (size_t)b * Cn * Hn * Wn;

    for (int ky = 0; ky < 3; ky++) {
        int yy = y - 1 + ky;
        if (yy < 0 || yy >= Hn) continue;
        for (int kx = 0; kx < 3; kx++) {
            int xx = xw - 1 + kx;
            if (xx < 0 || xx >= Wn) continue;
            int tap = ky * 3 + kx;
            const float* xc = xbase + yy * Wn + xx;          // stride Hn*Wn per c
            const float* wrow = wS + tap * Cn * 20;
#pragma unroll 4
            for (int c = 0; c < Cn; c++) {
                float a = __ldg(xc + (size_t)c * (Hn * Wn));
                unsigned long long ap = pack1(a);
                const float* wr = wrow + c * 20;              // 80B aligned
                ulonglong2 w01 = *(const ulonglong2*)(wr);
                ulonglong2 w23 = *(const ulonglong2*)(wr + 4);
                ulonglong2 w45 = *(const ulonglong2*)(wr + 8);
                ulonglong2 w67 = *(const ulonglong2*)(wr + 12);
                unsigned long long w8 = *(const unsigned long long*)(wr + 16);
                ffma2(acc[0], ap, w01.x);
                ffma2(acc[1], ap, w01.y);
                ffma2(acc[2], ap, w23.x);
                ffma2(acc[3], ap, w23.y);
                ffma2(acc[4], ap, w45.x);
                ffma2(acc[5], ap, w45.y);
                ffma2(acc[6], ap, w67.x);
                ffma2(acc[7], ap, w67.y);
                ffma2(acc[8], ap, w8);
            }
        }
    }

#pragma unroll
    for (int j = 0; j < 9; j++) {
        float2 v = unpk2(acc[j]);
        g_off[(2 * j) * NPIX + pid] = v.x;
        g_off[(2 * j + 1) * NPIX + pid] = v.y;
    }
}

// ---------------------------------------------------------------------------
// Kernel 4: deformable conv. CTA = 64 px (8w x 8h) x 64 o, 128 threads.
// Thread = 2 px (pg, pg+32) x 16 o (og*4 + 16q), f32x2 accumulators.
// grid (16, 16, 4) = 1024 CTAs, ~6 CTAs/SM (33.8 KB smem, <=85 regs).
// ---------------------------------------------------------------------------
#define TS_W 8
#define TS_H 8
#define TPX 64
#define SA_STRIDE 68

__global__ __launch_bounds__(128, 6) void deform_k(
    const float* __restrict__ bias,
    float* __restrict__ out)
{
    extern __shared__ float dsm[];
    float* sA = dsm;                        // 64 * 68 floats
    float* sW = dsm + TPX * SA_STRIDE;      // 64 * 64 floats

    int tid = threadIdx.x;
    int x0t = blockIdx.x * TS_W;
    int y0t = blockIdx.y * TS_H;
    int b = blockIdx.z;

    // gather mapping: 16 lanes per pixel (one float4 chunk each), 8 px / pass
    int gchunk = tid & 15;
    int gpx0 = tid >> 4;                    // 0..7
    int cc = gchunk * 4;

    // gemm mapping
    int og = tid & 3;                       // o = og*4 + 16q + {0..3}
    int pg = tid >> 2;                      // 0..31; px pair (pg, pg+32)

    unsigned long long acc0[8], acc1[8];
#pragma unroll
    for (int j = 0; j < 8; j++) { acc0[j] = 0ull; acc1[j] = 0ull; }

    const float* xb = g_xT + (size_t)b * Hn * Wn * Cn;

    for (int k = 0; k < KK; k++) {
        __syncthreads();

        // stage W_k[c][o]  (4096 floats, 8 float4 per thread)
        {
            const float4* src = (const float4*)(g_w2 + k * Cn * On);
            float4* dst = (float4*)sW;
#pragma unroll
            for (int r = 0; r < 8; r++) dst[tid + r * 128] = src[tid + r * 128];
        }

        // gather S_k
        int ky = k / 3, kx = k - ky * 3;
#pragma unroll
        for (int it = 0; it < 8; it++) {
            int p = it * 8 + gpx0;
            int lw = p & 7, lh = p >> 3;
            int gx = x0t + lw, gy = y0t + lh;
            int gpix = (b * Hn + gy) * Wn + gx;
            float offY = __ldg(g_off + (2 * k) * NPIX + gpix);
            float offX = __ldg(g_off + (2 * k + 1) * NPIX + gpix);
            float pfy = (float)(gy - 1 + ky) + offY;
            float pfx = (float)(gx - 1 + kx) + offX;
            float fy0 = floorf(pfy), fx0 = floorf(pfx);
            float wy1 = pfy - fy0, wx1 = pfx - fx0;
            float wy0 = 1.f - wy1, wx0 = 1.f - wx1;
            int iy0 = (int)fy0, ix0 = (int)fx0;
            int iy1 = iy0 + 1, ix1 = ix0 + 1;
            bool vy0 = (iy0 >= 0) & (iy0 < Hn);
            bool vy1 = (iy1 >= 0) & (iy1 < Hn);
            bool vx0 = (ix0 >= 0) & (ix0 < Wn);
            bool vx1 = (ix1 >= 0) & (ix1 < Wn);
            int cy0 = min(max(iy0, 0), Hn - 1);
            int cy1 = min(max(iy1, 0), Hn - 1);
            int cx0 = min(max(ix0, 0), Wn - 1);
            int cx1 = min(max(ix1, 0), Wn - 1);

            const float* bp = xb + cc;
            float4 r = make_float4(0.f, 0.f, 0.f, 0.f);
            if (vy0 & vx0) {
                float4 t = *(const float4*)(bp + (cy0 * Wn + cx0) * Cn);
                float w = wy0 * wx0;
                r.x += w * t.x; r.y += w * t.y; r.z += w * t.z; r.w += w * t.w;
            }
            if (vy0 & vx1) {
                float4 t = *(const float4*)(bp + (cy0 * Wn + cx1) * Cn);
                float w = wy0 * wx1;
                r.x += w * t.x; r.y += w * t.y; r.z += w * t.z; r.w += w * t.w;
            }
            if (vy1 & vx0) {
                float4 t = *(const float4*)(bp + (cy1 * Wn + cx0) * Cn);
                float w = wy1 * wx0;
                r.x += w * t.x; r.y += w * t.y; r.z += w * t.z; r.w += w * t.w;
            }
            if (vy1 & vx1) {
                float4 t = *(const float4*)(bp + (cy1 * Wn + cx1) * Cn);
                float w = wy1 * wx1;
                r.x += w * t.x; r.y += w * t.y; r.z += w * t.z; r.w += w * t.w;
            }
            *(float4*)(sA + p * SA_STRIDE + cc) = r;
        }

        __syncthreads();

        // rank-64 update (thread: 2 px x 16 o)
        const float* a0p = sA + pg * SA_STRIDE;
        const float* a1p = sA + (pg + 32) * SA_STRIDE;
        const float* bcol = sW + og * 4;
        for (int c = 0; c < Cn; c += 4) {
            float4 a0v = *(const float4*)(a0p + c);
            float4 a1v = *(const float4*)(a1p + c);
#pragma unroll
            for (int u = 0; u < 4; u++) {
                float av0 = (u == 0) ? a0v.x : (u == 1) ? a0v.y : (u == 2) ? a0v.z : a0v.w;
                float av1 = (u == 0) ? a1v.x : (u == 1) ? a1v.y : (u == 2) ? a1v.z : a1v.w;
                unsigned long long ap0 = pack1(av0);
                unsigned long long ap1 = pack1(av1);
                const float* br = bcol + (c + u) * On;
#pragma unroll
                for (int q = 0; q < 4; q++) {
                    ulonglong2 bv = *(const ulonglong2*)(br + q * 16);
                    ffma2(acc0[q * 2], ap0, bv.x);
                    ffma2(acc0[q * 2 + 1], ap0, bv.y);
                    ffma2(acc1[q * 2], ap1, bv.x);
                    ffma2(acc1[q * 2 + 1], ap1, bv.y);
                }
            }
        }
    }

    // epilogue: transpose through smem (reuse sA as [o][64]) for coalesced STG
    __syncthreads();
#pragma unroll
    for (int q = 0; q < 4; q++) {
#pragma unroll
        for (int s = 0; s < 2; s++) {
            int o = og * 4 + q * 16 + s * 2;
            float2 v0 = unpk2(acc0[q * 2 + s]);
            float2 v1 = unpk2(acc1[q * 2 + s]);
            sA[o * TPX + pg] = v0.x;
            sA[(o + 1) * TPX + pg] = v0.y;
            sA[o * TPX + pg + 32] = v1.x;
            sA[(o + 1) * TPX + pg + 32] = v1.y;
        }
    }
    __syncthreads();

#pragma unroll
    for (int r = 0; r < 32; r++) {
        int i = r * 128 + tid;           // 0..4095
        int o = i >> 6;
        int p = i & 63;
        int lw = p & 7, lh = p >> 3;
        float v = sA[o * TPX + p] + __ldg(bias + o);
        out[(((size_t)b * On + o) * Hn + (y0t + lh)) * Wn + (x0t + lw)] = v;
    }
}

// ---------------------------------------------------------------------------
extern "C" void kernel_launch(void* const* d_in, const int* in_sizes, int n_in,
                              void* d_out, int out_size) {
    const float* x        = (const float*)d_in[0];   // (4,64,128,128)
    const float* offset_w = (const float*)d_in[1];   // (18,64,3,3)
    const float* offset_b = (const float*)d_in[2];   // (18,)
    const float* weight   = (const float*)d_in[3];   // (64,64,3,3)
    const float* bias     = (const float*)d_in[4];   // (64,)
    float* out = (float*)d_out;                      // (4,64,128,128)

    cudaFuncSetAttribute(deform_k, cudaFuncAttributeMaxDynamicSharedMemorySize,
                         (TPX * SA_STRIDE + Cn * On) * 4);

    transpose_k<<<dim3(Wn / 32, Cn / 32, Bn * Hn), dim3(32, 8)>>>(x);
    prep_w_k<<<(KK * Cn * On + 255) / 256, 256>>>(weight);
    offset_conv_k<<<(NPIX) / 256, 256>>>(x, offset_w, offset_b);
    deform_k<<<dim3(Wn / TS_W, Hn / TS_H, Bn), 128,
               (TPX * SA_STRIDE + Cn * On) * 4>>>(bias, out);
}

// round 12
// speedup vs baseline: 2.6608x; 1.6511x over previous
#include <cuda_runtime.h>
#include <cuda_bf16.h>
#include <cstdint>

#define Bn 4
#define Cn 64
#define On 64
#define Hn 128
#define Wn 128
#define KK 9
#define NPIX (Bn * Hn * Wn)

// Scratch (device globals: no allocation allowed)
__device__ __align__(16) float g_xT[(size_t)Bn * Hn * Wn * Cn];  // x in NHWC
__device__ __align__(16) float g_off[18 * NPIX];                 // offsets [ch][pix]
__device__ __align__(16) unsigned short g_wbf[KK * 2 * Cn * On]; // per tap: swizzled hi tile (4096 u16) then lo tile

// ---------------- helpers ----------------
__device__ __forceinline__ uint32_t smem_u32(const void* p) {
    uint32_t a;
    asm("{ .reg .u64 t; cvta.to.shared.u64 t, %1; cvt.u32.u64 %0, t; }" : "=r"(a) : "l"(p));
    return a;
}
__device__ __forceinline__ uint32_t bf16x2_of(float lo, float hi) {
    uint32_t r;
    asm("cvt.rn.bf16x2.f32 %0, %1, %2;" : "=r"(r) : "f"(hi), "f"(lo));
    return r;
}
__device__ __forceinline__ void ldm_x4(uint32_t* r, uint32_t addr) {
    asm volatile("ldmatrix.sync.aligned.m8n8.x4.shared.b16 {%0,%1,%2,%3}, [%4];"
                 : "=r"(r[0]), "=r"(r[1]), "=r"(r[2]), "=r"(r[3]) : "r"(addr));
}
__device__ __forceinline__ void mma_bf16(float4& d, const uint32_t* a, uint32_t b0, uint32_t b1) {
    asm volatile(
        "mma.sync.aligned.m16n8k16.row.col.f32.bf16.bf16.f32 "
        "{%0,%1,%2,%3}, {%4,%5,%6,%7}, {%8,%9}, {%0,%1,%2,%3};"
        : "+f"(d.x), "+f"(d.y), "+f"(d.z), "+f"(d.w)
        : "r"(a[0]), "r"(a[1]), "r"(a[2]), "r"(a[3]), "r"(b0), "r"(b1));
}
__device__ __forceinline__ unsigned long long pack2(float lo, float hi) {
    unsigned long long r;
    asm("mov.b64 %0, {%1,%2};" : "=l"(r) : "f"(lo), "f"(hi));
    return r;
}
__device__ __forceinline__ unsigned long long pack1(float a) { return pack2(a, a); }
__device__ __forceinline__ void ffma2(unsigned long long& d, unsigned long long a, unsigned long long b) {
    asm("fma.rn.f32x2 %0, %1, %2, %0;" : "+l"(d) : "l"(a), "l"(b));
}
__device__ __forceinline__ float2 unpk2(unsigned long long v) {
    float2 r;
    asm("mov.b64 {%0,%1}, %2;" : "=f"(r.x), "=f"(r.y) : "l"(v));
    return r;
}

// ---------------------------------------------------------------------------
// Kernel 1: NCHW -> NHWC transpose of x
// ---------------------------------------------------------------------------
__global__ void transpose_k(const float* __restrict__ x) {
    __shared__ float tile[32][33];
    int w0 = blockIdx.x * 32;
    int c0 = blockIdx.y * 32;
    int bh = blockIdx.z;
    int b = bh >> 7, h = bh & 127;
    int tx = threadIdx.x, ty = threadIdx.y;
#pragma unroll
    for (int i = 0; i < 4; i++) {
        int c = c0 + ty + i * 8;
        tile[ty + i * 8][tx] = x[(((size_t)b * Cn + c) * Hn + h) * Wn + (w0 + tx)];
    }
    __syncthreads();
#pragma unroll
    for (int i = 0; i < 4; i++) {
        int w = w0 + ty + i * 8;
        g_xT[(((size_t)b * Hn + h) * Wn + w) * Cn + (c0 + tx)] = tile[tx][ty + i * 8];
    }
}

// ---------------------------------------------------------------------------
// Kernel 2: weight (O,C,3,3) -> per-tap bf16 hi/lo swizzled B tiles.
// B[o][c], 128B rows, XOR swizzle: off ^ ((off>>3)&0x70).
// ---------------------------------------------------------------------------
__global__ void prep_wbf(const float* __restrict__ weight) {
    int d = blockIdx.x * 256 + threadIdx.x;
    if (d >= KK * Cn * On) return;
    int k = d >> 12;
    int rem = d & 4095;
    int c = rem >> 6;
    int o = rem & 63;
    float f = weight[(o * Cn + c) * KK + k];
    __nv_bfloat16 h = __float2bfloat16(f);
    float hf = __bfloat162float(h);
    __nv_bfloat16 l = __float2bfloat16(f - hf);
    uint32_t off = (uint32_t)o * 128 + (uint32_t)c * 2;
    uint32_t sw = off ^ ((off >> 3) & 0x70);
    g_wbf[(size_t)k * 8192 + (sw >> 1)] = __bfloat16_as_ushort(h);
    g_wbf[(size_t)k * 8192 + 4096 + (sw >> 1)] = __bfloat16_as_ushort(l);
}

// ---------------------------------------------------------------------------
// Kernel 3: offset conv (3x3 SAME, 64 -> 18 ch), NCHW x reads, f32x2 accum.
// Output plane layout g_off[ch][pix]. (unchanged from R10)
// ---------------------------------------------------------------------------
__global__ __launch_bounds__(256) void offset_conv_k(
    const float* __restrict__ x,
    const float* __restrict__ offset_w,
    const float* __restrict__ offset_b)
{
    __shared__ float wS[KK * Cn * 20];

    int tid = threadIdx.x;
    for (int s = tid; s < KK * Cn * 18; s += 256) {
        int j = s % 18;
        int t2 = s / 18;
        int c = t2 & 63;
        int tap = t2 >> 6;
        wS[t2 * 20 + j] = offset_w[(j * Cn + c) * KK + tap];
    }
    __syncthreads();

    int pid = blockIdx.x * 256 + tid;
    int b = pid >> 14;
    int y = (pid >> 7) & 127;
    int xw = pid & 127;

    unsigned long long acc[9];
#pragma unroll
    for (int j = 0; j < 9; j++) acc[j] = pack2(offset_b[2 * j], offset_b[2 * j + 1]);

    const float* xbase = x + (size_t)b * Cn * Hn * Wn;

    for (int ky = 0; ky < 3; ky++) {
        int yy = y - 1 + ky;
        if (yy < 0 || yy >= Hn) continue;
        for (int kx = 0; kx < 3; kx++) {
            int xx = xw - 1 + kx;
            if (xx < 0 || xx >= Wn) continue;
            int tap = ky * 3 + kx;
            const float* xc = xbase + yy * Wn + xx;
            const float* wrow = wS + tap * Cn * 20;
#pragma unroll 4
            for (int c = 0; c < Cn; c++) {
                float a = __ldg(xc + (size_t)c * (Hn * Wn));
                unsigned long long ap = pack1(a);
                const float* wr = wrow + c * 20;
                ulonglong2 w01 = *(const ulonglong2*)(wr);
                ulonglong2 w23 = *(const ulonglong2*)(wr + 4);
                ulonglong2 w45 = *(const ulonglong2*)(wr + 8);
                ulonglong2 w67 = *(const ulonglong2*)(wr + 12);
                unsigned long long w8 = *(const unsigned long long*)(wr + 16);
                ffma2(acc[0], ap, w01.x);
                ffma2(acc[1], ap, w01.y);
                ffma2(acc[2], ap, w23.x);
                ffma2(acc[3], ap, w23.y);
                ffma2(acc[4], ap, w45.x);
                ffma2(acc[5], ap, w45.y);
                ffma2(acc[6], ap, w67.x);
                ffma2(acc[7], ap, w67.y);
                ffma2(acc[8], ap, w8);
            }
        }
    }

#pragma unroll
    for (int j = 0; j < 9; j++) {
        float2 v = unpk2(acc[j]);
        g_off[(2 * j) * NPIX + pid] = v.x;
        g_off[(2 * j + 1) * NPIX + pid] = v.y;
    }
}

// ---------------------------------------------------------------------------
// Kernel 4: deformable conv via mma.sync bf16 hi/lo compensation.
// CTA = 128 px (16w x 8h) x 64 o, 256 threads (8 warps).
// Per tap: gather bilinear fp32 -> bf16 hi/lo swizzled smem A; stage B hi/lo;
// each warp: 16px x 64o via ldmatrix + 96 mma (4 ksteps x 4 tile-pairs x 6).
// ---------------------------------------------------------------------------
#define TS_W 16
#define TS_H 8
#define SM_AHI 1024
#define SM_ALO (1024 + 16384)
#define SM_BHI (1024 + 32768)
#define SM_BLO (1024 + 32768 + 8192)
#define SM_TOTAL (1024 + 32768 + 16384)   // 50176 B

__global__ __launch_bounds__(256, 3) void deform_k(
    const float* __restrict__ bias,
    float* __restrict__ out)
{
    extern __shared__ char dsm[];
    uint32_t smem_base = smem_u32(dsm);

    int tid = threadIdx.x;
    int wid = tid >> 5;
    int lane = tid & 31;
    int x0t = blockIdx.x * TS_W;
    int y0t = blockIdx.y * TS_H;
    int b = blockIdx.z;

    // gather mapping: 16 lanes per pixel, 16 px per pass, 8 passes
    int gchunk = tid & 15;
    int gpx0 = tid >> 4;          // 0..15
    int cc = gchunk * 4;

    // gemm mapping: warp wid handles px rows [wid*16, wid*16+16)
    int p_base = wid * 16;
    uint32_t xorv = (uint32_t)(lane & 7) << 4;
    // A ldmatrix address components (sel = lane>>3)
    int arow = (lane & 7) + ((lane >> 3) & 1) * 8;
    int acol16 = (lane >> 4) * 16;                 // +16B for sel 2,3
    // B ldmatrix address components
    int brow = ((lane >> 4) * 8) + (lane & 7);     // +8 rows for sel 2,3
    int bcol16 = ((lane >> 3) & 1) * 16;           // +16B for sel 1,3

    float4 dacc[8];
#pragma unroll
    for (int j = 0; j < 8; j++) dacc[j] = make_float4(0.f, 0.f, 0.f, 0.f);

    const float* xb = g_xT + (size_t)b * Hn * Wn * Cn;

    for (int k = 0; k < KK; k++) {
        __syncthreads();          // prior gemm done reading smem

        // --- stage B hi/lo (16 KB, already swizzled) ---
        {
            const float4* src = (const float4*)(g_wbf + (size_t)k * 8192);
            float4* dst = (float4*)(dsm + SM_BHI);
#pragma unroll
            for (int r = 0; r < 4; r++) dst[tid + r * 256] = src[tid + r * 256];
        }

        // --- gather + bf16 split into A tiles ---
        int ky = k / 3, kx = k - ky * 3;
#pragma unroll
        for (int it = 0; it < 8; it++) {
            int p = it * 16 + gpx0;
            int lw = p & 15, lh = p >> 4;
            int gx = x0t + lw, gy = y0t + lh;
            int gpix = (b * Hn + gy) * Wn + gx;
            float offY = __ldg(g_off + (2 * k) * NPIX + gpix);
            float offX = __ldg(g_off + (2 * k + 1) * NPIX + gpix);
            float pfy = (float)(gy - 1 + ky) + offY;
            float pfx = (float)(gx - 1 + kx) + offX;
            float fy0 = floorf(pfy), fx0 = floorf(pfx);
            float wy1 = pfy - fy0, wx1 = pfx - fx0;
            float wy0 = 1.f - wy1, wx0 = 1.f - wx1;
            int iy0 = (int)fy0, ix0 = (int)fx0;
            int iy1 = iy0 + 1, ix1 = ix0 + 1;
            bool vy0 = (iy0 >= 0) & (iy0 < Hn);
            bool vy1 = (iy1 >= 0) & (iy1 < Hn);
            bool vx0 = (ix0 >= 0) & (ix0 < Wn);
            bool vx1 = (ix1 >= 0) & (ix1 < Wn);
            int cy0 = min(max(iy0, 0), Hn - 1);
            int cy1 = min(max(iy1, 0), Hn - 1);
            int cx0 = min(max(ix0, 0), Wn - 1);
            int cx1 = min(max(ix1, 0), Wn - 1);

            const float* bp = xb + cc;
            float4 r = make_float4(0.f, 0.f, 0.f, 0.f);
            if (vy0 & vx0) {
                float4 t = *(const float4*)(bp + (cy0 * Wn + cx0) * Cn);
                float w = wy0 * wx0;
                r.x += w * t.x; r.y += w * t.y; r.z += w * t.z; r.w += w * t.w;
            }
            if (vy0 & vx1) {
                float4 t = *(const float4*)(bp + (cy0 * Wn + cx1) * Cn);
                float w = wy0 * wx1;
                r.x += w * t.x; r.y += w * t.y; r.z += w * t.z; r.w += w * t.w;
            }
            if (vy1 & vx0) {
                float4 t = *(const float4*)(bp + (cy1 * Wn + cx0) * Cn);
                float w = wy1 * wx0;
                r.x += w * t.x; r.y += w * t.y; r.z += w * t.z; r.w += w * t.w;
            }
            if (vy1 & vx1) {
                float4 t = *(const float4*)(bp + (cy1 * Wn + cx1) * Cn);
                float w = wy1 * wx1;
                r.x += w * t.x; r.y += w * t.y; r.z += w * t.z; r.w += w * t.w;
            }

            // split fp32 -> bf16 hi + bf16 lo
            uint32_t hi0 = bf16x2_of(r.x, r.y);
            uint32_t hi1 = bf16x2_of(r.z, r.w);
            float b0 = __uint_as_float(hi0 << 16);
            float b1 = __uint_as_float(hi0 & 0xFFFF0000u);
            float b2 = __uint_as_float(hi1 << 16);
            float b3 = __uint_as_float(hi1 & 0xFFFF0000u);
            uint32_t lo0 = bf16x2_of(r.x - b0, r.y - b1);
            uint32_t lo1 = bf16x2_of(r.z - b2, r.w - b3);

            uint32_t off = (uint32_t)p * 128 + (uint32_t)cc * 2;
            uint32_t sw = off ^ ((off >> 3) & 0x70);
            *(uint2*)(dsm + SM_AHI + sw) = make_uint2(hi0, hi1);
            *(uint2*)(dsm + SM_ALO + sw) = make_uint2(lo0, lo1);
        }

        __syncthreads();

        // --- per-warp HMMA: 16px x 64o, 3 compensation terms ---
#pragma unroll
        for (int ks = 0; ks < 4; ks++) {
            uint32_t aoff = (uint32_t)((p_base + arow) * 128 + ks * 32 + acol16) ^ xorv;
            uint32_t ah[4], al[4];
            ldm_x4(ah, smem_base + SM_AHI + aoff);
            ldm_x4(al, smem_base + SM_ALO + aoff);
#pragma unroll
            for (int jj = 0; jj < 4; jj++) {
                uint32_t boff = (uint32_t)((16 * jj + brow) * 128 + ks * 32 + bcol16) ^ xorv;
                uint32_t bh[4], bl[4];
                ldm_x4(bh, smem_base + SM_BHI + boff);
                ldm_x4(bl, smem_base + SM_BLO + boff);
                mma_bf16(dacc[2 * jj],     ah, bh[0], bh[1]);
                mma_bf16(dacc[2 * jj + 1], ah, bh[2], bh[3]);
                mma_bf16(dacc[2 * jj],     al, bh[0], bh[1]);
                mma_bf16(dacc[2 * jj + 1], al, bh[2], bh[3]);
                mma_bf16(dacc[2 * jj],     ah, bl[0], bl[1]);
                mma_bf16(dacc[2 * jj + 1], ah, bl[2], bl[3]);
            }
        }
    }

    // --- epilogue: stage D via smem (reuse A region as sD[o][128]) ---
    __syncthreads();
    float* sD = (float*)(dsm + SM_AHI);
    {
        int r0 = p_base + (lane >> 2);
        int r1 = r0 + 8;
#pragma unroll
        for (int j = 0; j < 8; j++) {
            int col = j * 8 + (lane & 3) * 2;
            sD[col * 128 + r0] = dacc[j].x;
            sD[(col + 1) * 128 + r0] = dacc[j].y;
            sD[col * 128 + r1] = dacc[j].z;
            sD[(col + 1) * 128 + r1] = dacc[j].w;
        }
    }
    __syncthreads();

#pragma unroll
    for (int r = 0; r < 32; r++) {
        int i = r * 256 + tid;           // 0..8191
        int o = i >> 7;
        int p = i & 127;
        int lw = p & 15, lh = p >> 4;
        float v = sD[o * 128 + p] + __ldg(bias + o);
        out[(((size_t)b * On + o) * Hn + (y0t + lh)) * Wn + (x0t + lw)] = v;
    }
}

// ---------------------------------------------------------------------------
extern "C" void kernel_launch(void* const* d_in, const int* in_sizes, int n_in,
                              void* d_out, int out_size) {
    const float* x        = (const float*)d_in[0];   // (4,64,128,128)
    const float* offset_w = (const float*)d_in[1];   // (18,64,3,3)
    const float* offset_b = (const float*)d_in[2];   // (18,)
    const float* weight   = (const float*)d_in[3];   // (64,64,3,3)
    const float* bias     = (const float*)d_in[4];   // (64,)
    float* out = (float*)d_out;                      // (4,64,128,128)

    cudaFuncSetAttribute(deform_k, cudaFuncAttributeMaxDynamicSharedMemorySize, SM_TOTAL);

    transpose_k<<<dim3(Wn / 32, Cn / 32, Bn * Hn), dim3(32, 8)>>>(x);
    prep_wbf<<<(KK * Cn * On + 255) / 256, 256>>>(weight);
    offset_conv_k<<<NPIX / 256, 256>>>(x, offset_w, offset_b);
    deform_k<<<dim3(Wn / TS_W, Hn / TS_H, Bn), 256, SM_TOTAL>>>(bias, out);
}